// round 2
// baseline (speedup 1.0000x reference)
#include <cuda_runtime.h>
#include <cstdint>

#define BB 2048
#define TT 512
#define KK 32

// 32 MB backpointer scratch (device global: allocation-free per harness rules)
__device__ unsigned char g_bp[(size_t)BB * TT * KK];

__global__ __launch_bounds__(128)
void crf_fused_kernel(const float* __restrict__ pot,     // [B,T,K]
                      const float* __restrict__ trans,   // [K,K]
                      const int*   __restrict__ seqlen,  // [B]
                      const int*   __restrict__ tags_in, // [B,T]
                      float*       __restrict__ out)     // [B*T + 2B] f32
{
    const unsigned FULL = 0xffffffffu;
    int warp = (blockIdx.x * blockDim.x + threadIdx.x) >> 5;
    int lane = threadIdx.x & 31;
    if (warp >= BB) return;
    const int b = warp;
    const int len = seqlen[b];

    const float LOG2E = 1.4426950408889634f;

    // Per-lane transition column Tr[:,lane] and exp(Tr[:,lane])
    float trc[KK], etrc[KK];
#pragma unroll
    for (int i = 0; i < KK; i++) {
        float tv = __ldg(&trans[i * KK + lane]);
        trc[i]  = tv;
        etrc[i] = exp2f(tv * LOG2E);
    }

    const float* pb = pot + (size_t)b * TT * KK;
    unsigned char* bpb = g_bp + (size_t)b * TT * KK;

    float alpha_v = pb[lane];   // viterbi alpha (state = lane)
    float alpha_l = alpha_v;    // log-norm alpha

#pragma unroll 4
    for (int t = 1; t < len; t++) {
        float p = pb[t * KK + lane];

        // ---- Viterbi: max/argmax over i of alpha_v[i] + Tr[i][lane]
        // strict '>' with ascending i == jnp.argmax first-occurrence semantics
        float best = -3.402823466e38f; int bi = 0;
#pragma unroll
        for (int i = 0; i < KK; i++) {
            float a = __shfl_sync(FULL, alpha_v, i);
            float s = a + trc[i];
            if (s > best) { best = s; bi = i; }
        }

        // ---- log-norm: m + log(sum_i exp(alpha_l[i]-m) * exp(Tr[i][lane]))
        float m = alpha_l;
#pragma unroll
        for (int o = 16; o; o >>= 1)
            m = fmaxf(m, __shfl_xor_sync(FULL, m, o));
        float v = exp2f((alpha_l - m) * LOG2E);
        float ssum = 0.f;
#pragma unroll
        for (int i = 0; i < KK; i++)
            ssum = fmaf(__shfl_sync(FULL, v, i), etrc[i], ssum);

        alpha_v = p + best;
        alpha_l = p + m + __logf(ssum);
        bpb[t * KK + lane] = (unsigned char)bi;
    }

    // ---- best_score / last_tag (first-occurrence argmax over lanes)
    float best = -3.402823466e38f; int last_tag = 0;
#pragma unroll
    for (int i = 0; i < KK; i++) {
        float a = __shfl_sync(FULL, alpha_v, i);
        if (a > best) { best = a; last_tag = i; }
    }

    // ---- log_norm = logsumexp over lanes of alpha_l
    float m = alpha_l;
#pragma unroll
    for (int o = 16; o; o >>= 1)
        m = fmaxf(m, __shfl_xor_sync(FULL, m, o));
    float v = exp2f((alpha_l - m) * LOG2E);
#pragma unroll
    for (int o = 16; o; o >>= 1)
        v += __shfl_xor_sync(FULL, v, o);
    float log_norm = m + __logf(v);

    // ---- sequence score (gold path)
    const int* ti = tags_in + (size_t)b * TT;
    float sscore = 0.f;
    for (int t = lane; t < TT; t += 32) {
        int tg = ti[t];
        if (t < len)     sscore += pb[t * KK + tg];
        if (t < len - 1) sscore += __ldg(&trans[tg * KK + ti[t + 1]]);
    }
#pragma unroll
    for (int o = 16; o; o >>= 1)
        sscore += __shfl_xor_sync(FULL, sscore, o);

    // ---- outputs: [tags as f32 (B*T)] [best_score (B)] [log_likelihood (B)]
    float* out_tags = out;
    // tags[t] = last_tag for t >= len-1 (masked region collapses to identity bps)
    for (int t = len - 1 + lane; t < TT; t += 32)
        out_tags[(size_t)b * TT + t] = (float)last_tag;

    // make lane-private bp writes visible to lane 0 before backtrace
    __threadfence_block();
    __syncwarp(FULL);

    if (lane == 0) {
        int tg = last_tag;
        for (int t = len - 2; t >= 0; t--) {
            tg = bpb[(t + 1) * KK + tg];
            out_tags[(size_t)b * TT + t] = (float)tg;
        }
        out[(size_t)BB * TT + b]      = best;
        out[(size_t)BB * TT + BB + b] = sscore - log_norm;
    }
}

extern "C" void kernel_launch(void* const* d_in, const int* in_sizes, int n_in,
                              void* d_out, int out_size) {
    const float* pot    = (const float*)d_in[0];  // potentials [B,T,K]
    const float* trans  = (const float*)d_in[1];  // transitions [K,K]
    const int*   seqlen = (const int*)d_in[2];    // sequence_lengths [B]
    const int*   tags   = (const int*)d_in[3];    // tag_indices [B,T]
    float* out = (float*)d_out;

    // 2048 warps = one warp per sequence; 4 warps/block
    crf_fused_kernel<<<BB / 4, 128>>>(pot, trans, seqlen, tags, out);
}

// round 4
// speedup vs baseline: 1.0571x; 1.0571x over previous
#include <cuda_runtime.h>
#include <cstdint>

#define BB 2048
#define TT 512
#define KK 32
#define FULLM 0xffffffffu

// 32 MB backpointer scratch
__device__ unsigned char g_bp[(size_t)BB * TT * KK];

// ---- Viterbi step: smem-broadcast alphas, exact first-occurrence argmax tree
__device__ __forceinline__ void vstep(float* __restrict__ row,
                                      const float* __restrict__ pp,
                                      const float* __restrict__ trc,
                                      float& alpha,
                                      unsigned char* __restrict__ bp,
                                      int lane)
{
    row[lane] = alpha;
    float p = pp[lane];
    __syncwarp();
    float s[KK];
#pragma unroll
    for (int c = 0; c < 8; c++) {
        float4 a = *reinterpret_cast<const float4*>(row + 4 * c);
        s[4 * c + 0] = a.x + trc[4 * c + 0];
        s[4 * c + 1] = a.y + trc[4 * c + 1];
        s[4 * c + 2] = a.z + trc[4 * c + 2];
        s[4 * c + 3] = a.w + trc[4 * c + 3];
    }
    // tournament: strict '>' with left (lower-index) priority == jnp.argmax
    float v[16]; int ix[16];
#pragma unroll
    for (int k = 0; k < 16; k++) {
        bool g = s[2 * k + 1] > s[2 * k];
        v[k]  = g ? s[2 * k + 1] : s[2 * k];
        ix[k] = g ? 2 * k + 1 : 2 * k;
    }
#pragma unroll
    for (int half = 8; half >= 1; half >>= 1) {
#pragma unroll
        for (int k = 0; k < half; k++) {
            bool g = v[k + half] > v[k];
            v[k]  = g ? v[k + half] : v[k];
            ix[k] = g ? ix[k + half] : ix[k];
        }
    }
    alpha = p + v[0];
    bp[lane] = (unsigned char)ix[0];
}

// ---- log-norm step: normalizer = lane0 alpha (exact LSE, no max tree)
__device__ __forceinline__ void lstep(float* __restrict__ row,
                                      const float* __restrict__ pp,
                                      const float* __restrict__ etrc,
                                      float& alpha, int lane)
{
    const float LOG2E = 1.4426950408889634f;
    float m = __shfl_sync(FULLM, alpha, 0);
    float ev = exp2f((alpha - m) * LOG2E);
    row[lane] = ev;
    float p = pp[lane];
    __syncwarp();
    float a0 = 0.f, a1 = 0.f, a2 = 0.f, a3 = 0.f;
#pragma unroll
    for (int c = 0; c < 8; c++) {
        float4 a = *reinterpret_cast<const float4*>(row + 4 * c);
        a0 = fmaf(a.x, etrc[4 * c + 0], a0);
        a1 = fmaf(a.y, etrc[4 * c + 1], a1);
        a2 = fmaf(a.z, etrc[4 * c + 2], a2);
        a3 = fmaf(a.w, etrc[4 * c + 3], a3);
    }
    float ssum = (a0 + a1) + (a2 + a3);
    alpha = p + m + __logf(ssum);
}

__global__ __launch_bounds__(256)
void crf_fused_kernel(const float* __restrict__ pot,     // [B,T,K]
                      const float* __restrict__ trans,   // [K,K]
                      const int*   __restrict__ seqlen,  // [B]
                      const int*   __restrict__ tags_in, // [B,T]
                      float*       __restrict__ out)     // [B*T + 2B] f32
{
    __shared__ float sh[8][64];   // per warp: 2 x 32-float double-buffered rows

    const int wib  = threadIdx.x >> 5;          // warp in block (0..7)
    const int lane = threadIdx.x & 31;
    const int b    = blockIdx.x * 4 + (wib >> 1);  // sequence
    const int role = wib & 1;                      // 0 = viterbi, 1 = lognorm
    const int len  = seqlen[b];

    const float LOG2E = 1.4426950408889634f;
    const float* pb = pot + (size_t)b * TT * KK;
    float* row0 = &sh[wib][0];
    float* row1 = &sh[wib][32];
    float* out_tags = out;

    if (role == 0) {
        // ===================== Viterbi warp =====================
        float trc[KK];
#pragma unroll
        for (int i = 0; i < KK; i++) trc[i] = __ldg(&trans[i * KK + lane]);

        unsigned char* bpb = g_bp + (size_t)b * TT * KK;
        float alpha = pb[lane];

        int t = 1;
        for (; t + 1 < len; t += 2) {
            vstep(row0, pb + (size_t)t * KK,       trc, alpha, bpb + (size_t)t * KK,       lane);
            vstep(row1, pb + (size_t)(t + 1) * KK, trc, alpha, bpb + (size_t)(t + 1) * KK, lane);
        }
        if (t < len)
            vstep(row0, pb + (size_t)t * KK, trc, alpha, bpb + (size_t)t * KK, lane);

        // first-occurrence argmax over lanes
        float bv = alpha; int bi = lane;
#pragma unroll
        for (int o = 16; o; o >>= 1) {
            float ov = __shfl_xor_sync(FULLM, bv, o);
            int   oi = __shfl_xor_sync(FULLM, bi, o);
            if (ov > bv || (ov == bv && oi < bi)) { bv = ov; bi = oi; }
        }
        const int last_tag = bi;

        // tags[t] = last_tag for t >= len-1
        for (int tt2 = len - 1 + lane; tt2 < TT; tt2 += 32)
            out_tags[(size_t)b * TT + tt2] = (float)last_tag;

        __threadfence_block();
        __syncwarp(FULLM);

        if (lane == 0) {
            int tg = last_tag;
            for (int tt2 = len - 2; tt2 >= 0; tt2--) {
                tg = bpb[(size_t)(tt2 + 1) * KK + tg];
                out_tags[(size_t)b * TT + tt2] = (float)tg;
            }
            out[(size_t)BB * TT + b] = bv;   // best_score
        }
    } else {
        // ===================== log-norm + seq-score warp =====================
        float etrc[KK];
#pragma unroll
        for (int i = 0; i < KK; i++)
            etrc[i] = exp2f(__ldg(&trans[i * KK + lane]) * LOG2E);

        float alpha = pb[lane];

        int t = 1;
        for (; t + 1 < len; t += 2) {
            lstep(row0, pb + (size_t)t * KK,       etrc, alpha, lane);
            lstep(row1, pb + (size_t)(t + 1) * KK, etrc, alpha, lane);
        }
        if (t < len)
            lstep(row0, pb + (size_t)t * KK, etrc, alpha, lane);

        // exact logsumexp over lanes
        float m = alpha;
#pragma unroll
        for (int o = 16; o; o >>= 1)
            m = fmaxf(m, __shfl_xor_sync(FULLM, m, o));
        float v = exp2f((alpha - m) * LOG2E);
#pragma unroll
        for (int o = 16; o; o >>= 1)
            v += __shfl_xor_sync(FULLM, v, o);
        float log_norm = m + __logf(v);

        // sequence score (gold path)
        const int* ti = tags_in + (size_t)b * TT;
        float sscore = 0.f;
        for (int tt2 = lane; tt2 < TT; tt2 += 32) {
            int tg = ti[tt2];
            if (tt2 < len)     sscore += pb[(size_t)tt2 * KK + tg];
            if (tt2 < len - 1) sscore += __ldg(&trans[tg * KK + ti[tt2 + 1]]);
        }
#pragma unroll
        for (int o = 16; o; o >>= 1)
            sscore += __shfl_xor_sync(FULLM, sscore, o);

        if (lane == 0)
            out[(size_t)BB * TT + BB + b] = sscore - log_norm;  // log_likelihood
    }
}

extern "C" void kernel_launch(void* const* d_in, const int* in_sizes, int n_in,
                              void* d_out, int out_size) {
    const float* pot    = (const float*)d_in[0];
    const float* trans  = (const float*)d_in[1];
    const int*   seqlen = (const int*)d_in[2];
    const int*   tags   = (const int*)d_in[3];
    float* out = (float*)d_out;

    // 2 warps per sequence, 8 warps (4 sequences) per block
    crf_fused_kernel<<<BB / 4, 256>>>(pot, trans, seqlen, tags, out);
}

// round 9
// speedup vs baseline: 1.4731x; 1.3935x over previous
#include <cuda_runtime.h>
#include <cstdint>

#define BB 2048
#define TT 512
#define KK 32
#define CH 64
#define FULLM 0xffffffffu

// 128 MB alpha-row scratch (device global; no allocation)
__device__ float g_alpha[(size_t)BB * TT * KK];

// ---- packed f32x2 helpers
__device__ __forceinline__ unsigned long long add2(unsigned long long a, unsigned long long b) {
    unsigned long long r; asm("add.rn.f32x2 %0,%1,%2;" : "=l"(r) : "l"(a), "l"(b)); return r;
}
__device__ __forceinline__ unsigned long long fma2(unsigned long long a, unsigned long long b, unsigned long long c) {
    unsigned long long r; asm("fma.rn.f32x2 %0,%1,%2,%3;" : "=l"(r) : "l"(a), "l"(b), "l"(c)); return r;
}
__device__ __forceinline__ float2 unpk(unsigned long long a) {
    float2 f; asm("mov.b64 {%0,%1},%2;" : "=f"(f.x), "=f"(f.y) : "l"(a)); return f;
}
__device__ __forceinline__ unsigned long long pk(float x, float y) {
    unsigned long long r; asm("mov.b64 %0,{%1,%2};" : "=l"(r) : "f"(x), "f"(y)); return r;
}

// bundled warp argmax: first-occurrence (lowest index wins ties); result in all lanes
__device__ __forceinline__ void wargmax(float v, int i, float& bv, int& bi) {
    bv = v; bi = i;
#pragma unroll
    for (int o = 16; o; o >>= 1) {
        float ov = __shfl_xor_sync(FULLM, bv, o);
        int   oi = __shfl_xor_sync(FULLM, bi, o);
        if (ov > bv || (ov == bv && oi < bi)) { bv = ov; bi = oi; }
    }
}

// ---- Viterbi forward step: value-only max, store alpha_{t-1} row to global
// r2[c]   = (row[4c],   row[4c+1],  row[4c+2],  row[4c+3])   -> trc2[2c],   trc2[2c+1]
// r2[c+4] = (row[4c+16],row[4c+17], row[4c+18], row[4c+19])  -> trc2[2c+8], trc2[2c+9]
__device__ __forceinline__ void vstep(float* __restrict__ row,
                                      float p,
                                      const unsigned long long* __restrict__ trc2,
                                      float& alpha,
                                      float* __restrict__ galpha_prev_row,
                                      int lane)
{
    galpha_prev_row[lane] = alpha;   // alpha_{t-1}, needed by backtrace
    row[lane] = alpha;
    __syncwarp();
    const ulonglong2* r2 = reinterpret_cast<const ulonglong2*>(row);
    float best = -3.402823466e38f;
#pragma unroll
    for (int c = 0; c < 4; c++) {
        ulonglong2 qa = r2[c];
        ulonglong2 qb = r2[c + 4];
        float2 f0 = unpk(add2(qa.x, trc2[2 * c + 0]));
        float2 f1 = unpk(add2(qa.y, trc2[2 * c + 1]));
        float2 f2 = unpk(add2(qb.x, trc2[2 * c + 8]));
        float2 f3 = unpk(add2(qb.y, trc2[2 * c + 9]));
        float m0 = fmaxf(fmaxf(f0.x, f0.y), fmaxf(f1.x, f1.y));
        float m1 = fmaxf(fmaxf(f2.x, f2.y), fmaxf(f3.x, f3.y));
        best = fmaxf(best, fmaxf(m0, m1));
    }
    alpha = p + best;
}

// ---- log-norm step: true-max normalizer (accuracy), packed FMA reduce
__device__ __forceinline__ void lstep(float* __restrict__ row,
                                      float p,
                                      const unsigned long long* __restrict__ etr2,
                                      float& alpha, int lane)
{
    const float LOG2E = 1.4426950408889634f;
    float m = alpha;
#pragma unroll
    for (int o = 16; o; o >>= 1)
        m = fmaxf(m, __shfl_xor_sync(FULLM, m, o));
    float ev = exp2f((alpha - m) * LOG2E);
    row[lane] = ev;
    __syncwarp();
    const ulonglong2* r2 = reinterpret_cast<const ulonglong2*>(row);
    unsigned long long a0 = 0ull, a1 = 0ull, a2 = 0ull, a3 = 0ull;
#pragma unroll
    for (int c = 0; c < 4; c++) {
        ulonglong2 qa = r2[c];
        ulonglong2 qb = r2[c + 4];
        a0 = fma2(qa.x, etr2[2 * c + 0], a0);
        a1 = fma2(qa.y, etr2[2 * c + 1], a1);
        a2 = fma2(qb.x, etr2[2 * c + 8], a2);
        a3 = fma2(qb.y, etr2[2 * c + 9], a3);
    }
    float2 s = unpk(add2(add2(a0, a1), add2(a2, a3)));
    alpha = p + m + __logf(s.x + s.y);
}

__global__ __launch_bounds__(64, 13)
void crf_fused_kernel(const float* __restrict__ pot,     // [B,T,K]
                      const float* __restrict__ trans,   // [K,K]
                      const int*   __restrict__ seqlen,  // [B]
                      const int*   __restrict__ tags_in, // [B,T]
                      float*       __restrict__ out)     // [B*T + 2B] f32
{
    __shared__ float Trp[KK * 33];                     // padded Tr for backtrace
    __shared__ __align__(16) float vrow[2][KK];
    __shared__ __align__(16) float lrow[2][KK];
    __shared__ float btrows[CH * KK];                  // backtrace alpha chunk

    const int tid  = threadIdx.x;
    const int lane = tid & 31;
    const int role = tid >> 5;          // 0 = viterbi, 1 = lognorm
    const int b    = blockIdx.x;
    const int len  = seqlen[b];

    const float LOG2E = 1.4426950408889634f;
    const float* pb = pot + (size_t)b * TT * KK;
    float* out_tags = out;

    // padded transitions into smem (both warps), needed by warp0's backtrace
    for (int idx = tid; idx < KK * KK; idx += 64)
        Trp[(idx >> 5) * 33 + (idx & 31)] = trans[idx];
    __syncthreads();

    if (role == 0) {
        // ===================== Viterbi warp =====================
        // packed Tr columns: trc2[k] = (Tr[2k][lane], Tr[2k+1][lane])
        unsigned long long trc2[16];
#pragma unroll
        for (int k = 0; k < 16; k++)
            trc2[k] = pk(__ldg(&trans[(2 * k) * KK + lane]),
                         __ldg(&trans[(2 * k + 1) * KK + lane]));

        float* gab = g_alpha + (size_t)b * TT * KK;
        float alpha = pb[lane];

        int t = 1;
        for (; t + 1 < len; t += 2) {
            float pa = pb[(size_t)t * KK + lane];
            float pc = pb[(size_t)(t + 1) * KK + lane];
            vstep(vrow[0], pa, trc2, alpha, gab + (size_t)(t - 1) * KK, lane);
            vstep(vrow[1], pc, trc2, alpha, gab + (size_t)t * KK, lane);
        }
        if (t < len) {
            float pa = pb[(size_t)t * KK + lane];
            vstep(vrow[0], pa, trc2, alpha, gab + (size_t)(t - 1) * KK, lane);
        }

        // last_tag / best_score
        float bv; int bi;
        wargmax(alpha, lane, bv, bi);
        const int last_tag = bi;

        for (int tt = len - 1 + lane; tt < TT; tt += 32)
            out_tags[(size_t)b * TT + tt] = (float)last_tag;
        if (lane == 0)
            out[(size_t)BB * TT + b] = bv;   // best_score

        // make alpha-row STGs visible before backtrace reads
        __threadfence_block();
        __syncwarp(FULLM);

        // ---- backtrace: chunk alpha rows into smem, warp-cooperative argmax
        int j  = last_tag;
        int hi = len - 2;
        while (hi >= 0) {
            int lo = hi - (CH - 1); if (lo < 0) lo = 0;
            int n  = (hi - lo + 1) * KK;
            for (int k = lane; k < n; k += 32)
                btrows[k] = gab[(size_t)lo * KK + k];
            __syncwarp(FULLM);
            for (int tt = hi; tt >= lo; tt--) {
                float s = btrows[(tt - lo) * KK + lane] + Trp[lane * 33 + j];
                float mv; int mi;
                wargmax(s, lane, mv, mi);
                j = mi;
                if (lane == 0)
                    out_tags[(size_t)b * TT + tt] = (float)j;
            }
            __syncwarp(FULLM);
            hi = lo - 1;
        }
    } else {
        // ===================== log-norm + seq-score warp =====================
        unsigned long long etr2[16];
#pragma unroll
        for (int k = 0; k < 16; k++)
            etr2[k] = pk(exp2f(__ldg(&trans[(2 * k) * KK + lane]) * LOG2E),
                         exp2f(__ldg(&trans[(2 * k + 1) * KK + lane]) * LOG2E));

        float alpha = pb[lane];

        int t = 1;
        for (; t + 1 < len; t += 2) {
            float pa = pb[(size_t)t * KK + lane];
            float pc = pb[(size_t)(t + 1) * KK + lane];
            lstep(lrow[0], pa, etr2, alpha, lane);
            lstep(lrow[1], pc, etr2, alpha, lane);
        }
        if (t < len) {
            float pa = pb[(size_t)t * KK + lane];
            lstep(lrow[0], pa, etr2, alpha, lane);
        }

        // exact logsumexp over lanes
        float m = alpha;
#pragma unroll
        for (int o = 16; o; o >>= 1)
            m = fmaxf(m, __shfl_xor_sync(FULLM, m, o));
        float v = exp2f((alpha - m) * LOG2E);
#pragma unroll
        for (int o = 16; o; o >>= 1)
            v += __shfl_xor_sync(FULLM, v, o);
        float log_norm = m + __logf(v);

        // sequence score (gold path)
        const int* ti = tags_in + (size_t)b * TT;
        float sscore = 0.f;
        for (int tt = lane; tt < TT; tt += 32) {
            int tg = ti[tt];
            if (tt < len)     sscore += pb[(size_t)tt * KK + tg];
            if (tt < len - 1) sscore += __ldg(&trans[tg * KK + ti[tt + 1]]);
        }
#pragma unroll
        for (int o = 16; o; o >>= 1)
            sscore += __shfl_xor_sync(FULLM, sscore, o);

        if (lane == 0)
            out[(size_t)BB * TT + BB + b] = sscore - log_norm;
    }
}

extern "C" void kernel_launch(void* const* d_in, const int* in_sizes, int n_in,
                              void* d_out, int out_size) {
    const float* pot    = (const float*)d_in[0];
    const float* trans  = (const float*)d_in[1];
    const int*   seqlen = (const int*)d_in[2];
    const int*   tags   = (const int*)d_in[3];
    float* out = (float*)d_out;

    // one sequence per 64-thread block (viterbi warp + lognorm warp)
    crf_fused_kernel<<<BB, 64>>>(pot, trans, seqlen, tags, out);
}